// round 4
// baseline (speedup 1.0000x reference)
#include <cuda_runtime.h>
#include <math.h>

// Problem constants (B=4, S=4096, D=768)
#define D_HALF 768
#define V_HALF 192            // float4s per half-row
#define NT 192                // one float4 column per thread
#define NW 6                  // warps per block
#define R_WAVE 4              // rows per register wave
#define WAVES 2
#define ROWS_PER_BLOCK 8
#define LN_EPS 1e-5f
#define INV_N (1.0f / 1536.0f)

__device__ __forceinline__ float4 ldcs4(const float4* p) {
    float4 v;
    asm volatile("ld.global.cs.v4.f32 {%0,%1,%2,%3}, [%4];"
                 : "=f"(v.x), "=f"(v.y), "=f"(v.z), "=f"(v.w) : "l"(p));
    return v;
}
__device__ __forceinline__ void stcs4(float4* p, float4 v) {
    asm volatile("st.global.cs.v4.f32 [%0], {%1,%2,%3,%4};"
                 :: "l"(p), "f"(v.x), "f"(v.y), "f"(v.z), "f"(v.w));
}

__device__ __forceinline__ float4 warp_reduce4(float4 v) {
#pragma unroll
    for (int o = 16; o > 0; o >>= 1) {
        v.x += __shfl_down_sync(0xffffffffu, v.x, o);
        v.y += __shfl_down_sync(0xffffffffu, v.y, o);
        v.z += __shfl_down_sync(0xffffffffu, v.z, o);
        v.w += __shfl_down_sync(0xffffffffu, v.w, o);
    }
    return v;
}

__device__ __forceinline__ float hsum4(float4 v) { return (v.x + v.y) + (v.z + v.w); }
__device__ __forceinline__ float dot4(float4 a, float4 b) {
    return a.x*b.x + a.y*b.y + a.z*b.z + a.w*b.w;
}
__device__ __forceinline__ float4 mul4(float4 a, float4 b) {
    return make_float4(a.x*b.x, a.y*b.y, a.z*b.z, a.w*b.w);
}

// ---------------------------------------------------------------------------
// Single fused kernel. Each block:
//  1. loads gamma/beta/gate_w for its columns, computes gamma*w products in
//     registers, block-reduces the 4 row-independent constants
//  2. processes ROWS_PER_BLOCK rows in 2 register waves of 4:
//     single pass -> LN stats + gate dots -> softmax weight -> blend store
// ---------------------------------------------------------------------------
__global__ __launch_bounds__(NT, 5)
void attention_fusion_kernel(const float4* __restrict__ seq,
                             const float4* __restrict__ msa,
                             const float4* __restrict__ gamma,
                             const float4* __restrict__ beta,
                             const float4* __restrict__ gate_w,
                             const float*  __restrict__ gate_b,
                             float4* __restrict__ out) {
    __shared__ float4 shred[R_WAVE][NW];
    __shared__ float4 sh_const;     // x=S(g*w0), y=S(g*w1), z=S(b*w0)+b0, w=S(b*w1)+b1
    __shared__ float  sh_w0[R_WAVE];

    const int t = threadIdx.x;     // 0..191
    const int wid = t >> 5, lid = t & 31;

    // ---- per-block prologue: params + constants ----
    const float4 gs  = __ldg(gamma  + t);
    const float4 gm  = __ldg(gamma  + V_HALF + t);
    const float4 w0s = __ldg(gate_w + t);
    const float4 w0m = __ldg(gate_w + V_HALF + t);
    const float4 w1s = __ldg(gate_w + 2 * V_HALF + t);
    const float4 w1m = __ldg(gate_w + 3 * V_HALF + t);
    const float4 bs  = __ldg(beta   + t);
    const float4 bm  = __ldg(beta   + V_HALF + t);

    const float4 q0s = mul4(gs, w0s);
    const float4 q0m = mul4(gm, w0m);
    const float4 q1s = mul4(gs, w1s);
    const float4 q1m = mul4(gm, w1m);

    {
        float4 c;
        c.x = hsum4(q0s) + hsum4(q0m);
        c.y = hsum4(q1s) + hsum4(q1m);
        c.z = dot4(bs, w0s) + dot4(bm, w0m);
        c.w = dot4(bs, w1s) + dot4(bm, w1m);
        c = warp_reduce4(c);
        if (lid == 0) shred[0][wid] = c;
    }
    __syncthreads();
    if (wid == 0) {
        float4 a = (lid < NW) ? shred[0][lid] : make_float4(0.f, 0.f, 0.f, 0.f);
#pragma unroll
        for (int o = 4; o > 0; o >>= 1) {
            a.x += __shfl_down_sync(0xffffffffu, a.x, o);
            a.y += __shfl_down_sync(0xffffffffu, a.y, o);
            a.z += __shfl_down_sync(0xffffffffu, a.z, o);
            a.w += __shfl_down_sync(0xffffffffu, a.w, o);
        }
        if (lid == 0)
            sh_const = make_float4(a.x, a.y,
                                   a.z + __ldg(gate_b + 0),
                                   a.w + __ldg(gate_b + 1));
    }
    __syncthreads();

    // ---- main: 2 waves of 4 rows ----
    const long long base = (long long)blockIdx.x * ROWS_PER_BLOCK;
    const float4* sp = seq + base * V_HALF + t;
    const float4* mp = msa + base * V_HALF + t;
    float4*       op = out + base * V_HALF + t;

#pragma unroll
    for (int wv = 0; wv < WAVES; wv++) {
        float4 s[R_WAVE], m[R_WAVE];
#pragma unroll
        for (int r = 0; r < R_WAVE; r++) {
            s[r] = ldcs4(sp + (wv * R_WAVE + r) * V_HALF);
            m[r] = ldcs4(mp + (wv * R_WAVE + r) * V_HALF);
        }

        float4 acc[R_WAVE];
#pragma unroll
        for (int r = 0; r < R_WAVE; r++) {
            float4 sv = s[r], mv = m[r];
            float4 a;
            a.x = hsum4(sv) + hsum4(mv);
            a.y = dot4(sv, sv) + dot4(mv, mv);
            a.z = dot4(sv, q0s) + dot4(mv, q0m);
            a.w = dot4(sv, q1s) + dot4(mv, q1m);
            acc[r] = warp_reduce4(a);
        }
        if (lid == 0) {
#pragma unroll
            for (int r = 0; r < R_WAVE; r++) shred[r][wid] = acc[r];
        }
        __syncthreads();

        if (wid < R_WAVE) {
            float4 a = (lid < NW) ? shred[wid][lid]
                                  : make_float4(0.f, 0.f, 0.f, 0.f);
#pragma unroll
            for (int o = 4; o > 0; o >>= 1) {
                a.x += __shfl_down_sync(0xffffffffu, a.x, o);
                a.y += __shfl_down_sync(0xffffffffu, a.y, o);
                a.z += __shfl_down_sync(0xffffffffu, a.z, o);
                a.w += __shfl_down_sync(0xffffffffu, a.w, o);
            }
            if (lid == 0) {
                float mean = a.x * INV_N;
                float var  = fmaf(-mean, mean, a.y * INV_N);
                float rstd = rsqrtf(var + LN_EPS);
                float4 C = sh_const;
                float l0 = fmaf(rstd, a.z - mean * C.x, C.z);
                float l1 = fmaf(rstd, a.w - mean * C.y, C.w);
                sh_w0[wid] = 1.0f / (1.0f + __expf(l1 - l0));
            }
        }
        __syncthreads();

#pragma unroll
        for (int r = 0; r < R_WAVE; r++) {
            float w0 = sh_w0[r];
            float w1 = 1.0f - w0;
            float4 o;
            o.x = fmaf(w0, s[r].x, w1 * m[r].x);
            o.y = fmaf(w0, s[r].y, w1 * m[r].y);
            o.z = fmaf(w0, s[r].z, w1 * m[r].z);
            o.w = fmaf(w0, s[r].w, w1 * m[r].w);
            stcs4(op + (wv * R_WAVE + r) * V_HALF, o);
        }
    }
}

// ---------------------------------------------------------------------------
// Launch: single kernel, single graph node.
// ---------------------------------------------------------------------------
extern "C" void kernel_launch(void* const* d_in, const int* in_sizes, int n_in,
                              void* d_out, int out_size) {
    const float* seq    = (const float*)d_in[0];
    const float* msa    = (const float*)d_in[1];
    const float* gamma  = (const float*)d_in[2];
    const float* beta   = (const float*)d_in[3];
    const float* gate_w = (const float*)d_in[4];
    const float* gate_b = (const float*)d_in[5];
    float* out = (float*)d_out;

    int rows   = in_sizes[0] / D_HALF;          // B*S = 16384
    int blocks = rows / ROWS_PER_BLOCK;         // 2048

    attention_fusion_kernel<<<blocks, NT>>>((const float4*)seq,
                                            (const float4*)msa,
                                            (const float4*)gamma,
                                            (const float4*)beta,
                                            (const float4*)gate_w,
                                            gate_b,
                                            (float4*)out);
}